// round 1
// baseline (speedup 1.0000x reference)
#include <cuda_runtime.h>
#include <cuda_bf16.h>
#include <cstdint>

// Problem constants
#define B_   8
#define C_   256
#define H_   96
#define W_   96
#define HW_  (H_*W_)          // 9216
#define G_   4
#define CG_  64               // channels per group
#define S_   2
#define HO_  (H_*S_)          // 192
#define WO_  (W_*S_)          // 192
#define NOUT_ 32              // offset channels

// Scratch: per-output-pixel sampling coords (ix, iy), layout [n=b*4+gi][oy][ox]
__device__ float2 g_coords[B_ * G_ * HO_ * WO_];   // 1,179,648 float2 = 9.4 MB

// ---------------------------------------------------------------------------
// Kernel 1: offset head.  offset[b,o,h,w] = (sum_c x[b,c,h,w]*w_off[o,c] + b_off[o]) * 0.25
// then ix = clip(w + off_x, 0, 95), iy = clip(h + off_y, 0, 95) written to g_coords.
// Block: 96 x 2 threads = 192 (one thread per (h,w)); grid: (48, 8).
// ---------------------------------------------------------------------------
__global__ __launch_bounds__(192) void dysample_offset_kernel(
    const float* __restrict__ x,
    const float* __restrict__ w_off,
    const float* __restrict__ b_off)
{
    __shared__ __align__(16) float w_sh[NOUT_ * C_];   // 32 KB, natural [o][c]
    __shared__ float b_sh[NOUT_];

    const int tid = threadIdx.y * 96 + threadIdx.x;
    for (int i = tid; i < NOUT_ * C_; i += 192) w_sh[i] = w_off[i];
    if (tid < NOUT_) b_sh[tid] = b_off[tid];
    __syncthreads();

    const int b = blockIdx.y;
    const int h = blockIdx.x * 2 + threadIdx.y;
    const int w = threadIdx.x;

    const float* xp = x + (size_t)b * C_ * HW_ + h * W_ + w;

    float acc[NOUT_];
#pragma unroll
    for (int o = 0; o < NOUT_; o++) acc[o] = 0.f;

#pragma unroll 2
    for (int cb = 0; cb < C_; cb += 4) {
        const float xv0 = xp[(cb + 0) * HW_];
        const float xv1 = xp[(cb + 1) * HW_];
        const float xv2 = xp[(cb + 2) * HW_];
        const float xv3 = xp[(cb + 3) * HW_];
#pragma unroll
        for (int o = 0; o < NOUT_; o++) {
            const float4 wv = *(const float4*)&w_sh[o * C_ + cb];
            float t = acc[o];
            t = fmaf(xv0, wv.x, t);
            t = fmaf(xv1, wv.y, t);
            t = fmaf(xv2, wv.z, t);
            t = fmaf(xv3, wv.w, t);
            acc[o] = t;
        }
    }

    // Epilogue: o = dir*16 + gi*4 + sy*2 + sx ; dir 0 = x-offset, dir 1 = y-offset
    const float wf = (float)w;
    const float hf = (float)h;
#pragma unroll
    for (int gi = 0; gi < G_; gi++) {
#pragma unroll
        for (int sy = 0; sy < S_; sy++) {
#pragma unroll
            for (int sx = 0; sx < S_; sx++) {
                const int idx = gi * 4 + sy * 2 + sx;
                const float offx = (acc[idx]      + b_sh[idx])      * 0.25f;
                const float offy = (acc[16 + idx] + b_sh[16 + idx]) * 0.25f;
                float ix = wf + offx;
                float iy = hf + offy;
                ix = fminf(fmaxf(ix, 0.f), (float)(W_ - 1));
                iy = fminf(fmaxf(iy, 0.f), (float)(H_ - 1));
                const int n  = b * G_ + gi;
                const int oy = 2 * h + sy;
                const int ox = 2 * w + sx;
                g_coords[((size_t)n * HO_ + oy) * WO_ + ox] = make_float2(ix, iy);
            }
        }
    }
}

// ---------------------------------------------------------------------------
// Kernel 2: bilinear gather. One thread per (n, oy, ox), loops 64 channels.
// Block: 192 threads (one output row); grid: (192 rows, 32 n).
// ---------------------------------------------------------------------------
__global__ __launch_bounds__(192) void dysample_sample_kernel(
    const float* __restrict__ x,
    float* __restrict__ out)
{
    const int ox = threadIdx.x;
    const int oy = blockIdx.x;
    const int n  = blockIdx.y;          // 0..31
    const int b  = n >> 2;
    const int gi = n & 3;

    const float2 crd = g_coords[((size_t)n * HO_ + oy) * WO_ + ox];
    const float ixf = crd.x, iyf = crd.y;
    const float x0f = floorf(ixf), y0f = floorf(iyf);
    const int xi0 = (int)x0f, yi0 = (int)y0f;
    const float wx = ixf - x0f, wy = iyf - y0f;
    const int xi1 = min(xi0 + 1, W_ - 1);
    const int yi1 = min(yi0 + 1, H_ - 1);

    const float w00 = (1.f - wy) * (1.f - wx);
    const float w01 = (1.f - wy) * wx;
    const float w10 = wy * (1.f - wx);
    const float w11 = wy * wx;

    const int i00 = yi0 * W_ + xi0;
    const int i01 = yi0 * W_ + xi1;
    const int i10 = yi1 * W_ + xi0;
    const int i11 = yi1 * W_ + xi1;

    const float* p = x + (size_t)(b * C_ + gi * CG_) * HW_;
    float* op = out + ((size_t)(b * C_ + gi * CG_) * HO_ + oy) * WO_ + ox;

#pragma unroll 8
    for (int c = 0; c < CG_; c++) {
        const float v00 = __ldg(p + i00);
        const float v01 = __ldg(p + i01);
        const float v10 = __ldg(p + i10);
        const float v11 = __ldg(p + i11);
        float v = w00 * v00;
        v = fmaf(w01, v01, v);
        v = fmaf(w10, v10, v);
        v = fmaf(w11, v11, v);
        *op = v;
        p  += HW_;
        op += HO_ * WO_;
    }
}

// ---------------------------------------------------------------------------
extern "C" void kernel_launch(void* const* d_in, const int* in_sizes, int n_in,
                              void* d_out, int out_size)
{
    const float* x     = (const float*)d_in[0];
    const float* w_off = (const float*)d_in[1];
    const float* b_off = (const float*)d_in[2];
    float* out = (float*)d_out;

    dysample_offset_kernel<<<dim3(48, B_), dim3(96, 2)>>>(x, w_off, b_off);
    dysample_sample_kernel<<<dim3(HO_, B_ * G_), dim3(WO_)>>>(x, out);
}